// round 9
// baseline (speedup 1.0000x reference)
#include <cuda_runtime.h>
#include <cuda_fp16.h>
#include <cstdint>
#include <cstddef>

// Problem dims (fixed by the reference)
static constexpr int M_DIM  = 512;    // B*S
static constexpr int K_DIM  = 4096;   // IN
static constexpr int N_DIM  = 11008;  // OUT
static constexpr int MTILE  = 128;
static constexpr int NTILE  = 64;     // 2 CTAs/SM
static constexpr int KSLAB  = 64;     // K per pipeline slab
static constexpr int NSLABS = K_DIM / KSLAB;   // 64
static constexpr int STAGES = 3;      // cp.async pipeline depth
static constexpr int THREADS = 256;   // 8 warps: 4(m) x 2(n), 32x32 each

// Pre-converted operands (exact: W = q-128 exactly representable in fp16;
// A rounds f32->f16 once)
__device__ __half g_A[M_DIM * K_DIM];           // 4 MB
__device__ __half g_W[(size_t)N_DIM * K_DIM];   // 90 MB static scratch

// ------------------------------------------------------------------ helpers
__device__ __forceinline__ uint32_t smem_u32(const void* p) {
    uint32_t r;
    asm("{ .reg .u64 t; cvta.to.shared.u64 t, %1; cvt.u32.u64 %0, t; }"
        : "=r"(r) : "l"(p));
    return r;
}

// XOR swizzle on 128B rows (16B chunks) -> conflict-free ldmatrix
#define SWZ(o) ((o) ^ (((o) >> 3) & 0x70))

__device__ __forceinline__ void ldsm_x4(uint32_t& r0, uint32_t& r1,
                                        uint32_t& r2, uint32_t& r3, uint32_t a) {
    asm volatile("ldmatrix.sync.aligned.m8n8.x4.shared.b16 {%0,%1,%2,%3}, [%4];"
                 : "=r"(r0), "=r"(r1), "=r"(r2), "=r"(r3) : "r"(a));
}

__device__ __forceinline__ void mma16816(float* d, const uint32_t* a,
                                         uint32_t b0, uint32_t b1) {
    asm volatile(
        "mma.sync.aligned.m16n8k16.row.col.f32.f16.f16.f32 "
        "{%0,%1,%2,%3}, {%4,%5,%6,%7}, {%8,%9}, {%0,%1,%2,%3};"
        : "+f"(d[0]), "+f"(d[1]), "+f"(d[2]), "+f"(d[3])
        : "r"(a[0]), "r"(a[1]), "r"(a[2]), "r"(a[3]), "r"(b0), "r"(b1));
}

// ------------------------------------------------------------------ SMEM layout
// stage: A panel (128 rows x 128B) + W panel (64 rows x 128B) = 24 KB
static constexpr int W_OFF       = 16384;
static constexpr int STAGE_BYTES = 24576;
static constexpr int SMEM_BYTES  = STAGES * STAGE_BYTES + 1024;  // 74752: 2/SM

// ------------------------------------------------------------------ convert kernels
__global__ void convert_A_kernel(const float* __restrict__ in) {
    int n4 = (M_DIM * K_DIM) / 4;
    int i = blockIdx.x * blockDim.x + threadIdx.x;
    if (i >= n4) return;
    float4 v = reinterpret_cast<const float4*>(in)[i];
    __half2 h0 = __floats2half2_rn(v.x, v.y);
    __half2 h1 = __floats2half2_rn(v.z, v.w);
    uint2 u;
    u.x = *reinterpret_cast<uint32_t*>(&h0);
    u.y = *reinterpret_cast<uint32_t*>(&h1);
    reinterpret_cast<uint2*>(g_A)[i] = u;
}

// W int32 -> exact (q-128) fp16, streaming (DRAM-bound)
__global__ void convert_W_kernel(const int4* __restrict__ qw) {
    size_t n4 = ((size_t)N_DIM * K_DIM) / 4;
    size_t i = (size_t)blockIdx.x * blockDim.x + threadIdx.x;
    if (i >= n4) return;
    int4 q = qw[i];
    __half2 h0 = __halves2half2(__int2half_rn(q.x - 128), __int2half_rn(q.y - 128));
    __half2 h1 = __halves2half2(__int2half_rn(q.z - 128), __int2half_rn(q.w - 128));
    uint2 u;
    u.x = *reinterpret_cast<uint32_t*>(&h0);
    u.y = *reinterpret_cast<uint32_t*>(&h1);
    reinterpret_cast<uint2*>(g_W)[i] = u;
}

// ------------------------------------------------------------------ GEMM
// issue one slab (A 128x64 + W 64x64 halves) via cp.async; one commit group
__device__ __forceinline__ void issue_slab(const __half* __restrict__ Abase,
                                           const __half* __restrict__ Wbase,
                                           int s, uint32_t stage, int tid) {
    const int kofs = s * KSLAB;
    // A: 128 rows x 8 chunks of 16B -> 4 per thread
#pragma unroll
    for (int i = 0; i < 4; i++) {
        int li = i * 256 + tid, r = li >> 3, c = li & 7;
        const __half* src = Abase + (size_t)r * K_DIM + kofs + c * 8;
        uint32_t dst = stage + SWZ(r * 128 + c * 16);
        asm volatile("cp.async.cg.shared.global [%0], [%1], 16;" :: "r"(dst), "l"(src));
    }
    // W: 64 rows x 8 chunks of 16B -> 2 per thread
#pragma unroll
    for (int i = 0; i < 2; i++) {
        int li = i * 256 + tid, r = li >> 3, c = li & 7;
        const __half* src = Wbase + (size_t)r * K_DIM + kofs + c * 8;
        uint32_t dst = stage + W_OFF + SWZ(r * 128 + c * 16);
        asm volatile("cp.async.cg.shared.global [%0], [%1], 16;" :: "r"(dst), "l"(src));
    }
    asm volatile("cp.async.commit_group;" ::: "memory");
}

// load one k-step's fragments (A 32x16, B 32x16) for this warp
__device__ __forceinline__ void load_frags(uint32_t a_sm, uint32_t w_sm, int ks,
                                           int lane, int wm, int wn,
                                           uint32_t a[2][4], uint32_t b[4][2]) {
    const int chunk = ks * 2 + (lane >> 4);
#pragma unroll
    for (int mt = 0; mt < 2; mt++) {
        int row = wm * 32 + mt * 16 + (lane & 15);
        ldsm_x4(a[mt][0], a[mt][1], a[mt][2], a[mt][3],
                a_sm + SWZ(row * 128 + chunk * 16));
    }
#pragma unroll
    for (int j = 0; j < 2; j++) {
        int row = wn * 32 + j * 16 + (lane & 15);
        uint32_t t0, t1, t2, t3;
        ldsm_x4(t0, t1, t2, t3, w_sm + SWZ(row * 128 + chunk * 16));
        b[j * 2 + 0][0] = t0;  b[j * 2 + 1][0] = t1;
        b[j * 2 + 0][1] = t2;  b[j * 2 + 1][1] = t3;
    }
}

__global__ void __launch_bounds__(THREADS, 2)
qlinear_hmma_kernel(const float* __restrict__ scale,
                    const float* __restrict__ bias, float* __restrict__ out) {
    extern __shared__ char smem_raw[];
    const uint32_t smem = (smem_u32(smem_raw) + 1023u) & ~1023u;

    const int tid  = threadIdx.x;
    const int wid  = tid >> 5;
    const int lane = tid & 31;
    const int wm   = wid >> 1;          // 0..3 : 32-row M strip
    const int wn   = wid & 1;           // 0..1 : 32-col N strip
    const int m0   = blockIdx.x * MTILE;    // m fastest -> weight L2 reuse
    const int n0   = blockIdx.y * NTILE;

    const __half* Abase = g_A + (size_t)m0 * K_DIM;
    const __half* Wbase = g_W + (size_t)n0 * K_DIM;

    float acc[2][4][4];
#pragma unroll
    for (int i = 0; i < 2; i++)
#pragma unroll
        for (int j = 0; j < 4; j++)
#pragma unroll
            for (int e = 0; e < 4; e++) acc[i][j][e] = 0.f;

    // ---- prologue: fill pipeline with slabs 0,1 --------------------------
    issue_slab(Abase, Wbase, 0, smem, tid);
    issue_slab(Abase, Wbase, 1, smem + STAGE_BYTES, tid);

    // ---- main loop: 3-stage cp.async, k-step fragment double buffer ------
#pragma unroll 1
    for (int s = 0; s < NSLABS; s++) {
        const uint32_t a_sm = smem + (s % STAGES) * STAGE_BYTES;
        const uint32_t w_sm = a_sm + W_OFF;

        asm volatile("cp.async.wait_group 1;" ::: "memory");   // slab s arrived
        __syncthreads();   // all warps done with stage (s-1)%3 == (s+2)%3

        if (s + 2 < NSLABS)
            issue_slab(Abase, Wbase, s + 2,
                       smem + ((s + 2) % STAGES) * STAGE_BYTES, tid);

        uint32_t a[2][2][4], b[2][4][2];
        load_frags(a_sm, w_sm, 0, lane, wm, wn, a[0], b[0]);
#pragma unroll
        for (int ks = 0; ks < 4; ks++) {
            const int cur = ks & 1;
            if (ks < 3)
                load_frags(a_sm, w_sm, ks + 1, lane, wm, wn, a[cur ^ 1], b[cur ^ 1]);
#pragma unroll
            for (int mt = 0; mt < 2; mt++)
#pragma unroll
                for (int nt = 0; nt < 4; nt++)
                    mma16816(acc[mt][nt], a[cur][mt], b[cur][nt][0], b[cur][nt][1]);
        }
    }

    // ---- epilogue: scale*acc + bias -> out ------------------------------
    const int ncb = n0 + wn * 32;
    float sc[4][2], bs[4][2];
#pragma unroll
    for (int nt = 0; nt < 4; nt++) {
#pragma unroll
        for (int e = 0; e < 2; e++) {
            int col = ncb + nt * 8 + (lane & 3) * 2 + e;
            sc[nt][e] = __ldg(&scale[col]);
            bs[nt][e] = __ldg(&bias[col]);
        }
    }
#pragma unroll
    for (int mt = 0; mt < 2; mt++) {
        int row = m0 + wm * 32 + mt * 16 + (lane >> 2);
#pragma unroll
        for (int nt = 0; nt < 4; nt++) {
            int col = ncb + nt * 8 + (lane & 3) * 2;
            float2 v0, v1;
            v0.x = acc[mt][nt][0] * sc[nt][0] + bs[nt][0];
            v0.y = acc[mt][nt][1] * sc[nt][1] + bs[nt][1];
            v1.x = acc[mt][nt][2] * sc[nt][0] + bs[nt][0];
            v1.y = acc[mt][nt][3] * sc[nt][1] + bs[nt][1];
            *reinterpret_cast<float2*>(out + (size_t)row * N_DIM + col)       = v0;
            *reinterpret_cast<float2*>(out + (size_t)(row + 8) * N_DIM + col) = v1;
        }
    }
}

// ------------------------------------------------------------------ launch
extern "C" void kernel_launch(void* const* d_in, const int* in_sizes, int n_in,
                              void* d_out, int out_size) {
    (void)in_sizes; (void)n_in; (void)out_size;
    const float* input = (const float*)d_in[0];
    const int4*  W     = (const int4*)d_in[1];
    const float* scale = (const float*)d_in[2];
    const float* bias  = (const float*)d_in[3];
    float* out = (float*)d_out;

    convert_A_kernel<<<(M_DIM * K_DIM / 4 + 255) / 256, 256>>>(input);

    size_t w4 = ((size_t)N_DIM * K_DIM) / 4;
    convert_W_kernel<<<(unsigned)((w4 + 255) / 256), 256>>>(W);

    cudaFuncSetAttribute(qlinear_hmma_kernel,
                         cudaFuncAttributeMaxDynamicSharedMemorySize, SMEM_BYTES);
    dim3 grid(M_DIM / MTILE, N_DIM / NTILE);   // m fastest: weight L2 reuse
    qlinear_hmma_kernel<<<grid, THREADS, SMEM_BYTES>>>(scale, bias, out);
}

// round 10
// speedup vs baseline: 1.0143x; 1.0143x over previous
#include <cuda_runtime.h>
#include <cuda_fp16.h>
#include <cstdint>
#include <cstddef>

// Problem dims (fixed by the reference)
static constexpr int M_DIM  = 512;    // B*S
static constexpr int K_DIM  = 4096;   // IN
static constexpr int N_DIM  = 11008;  // OUT
static constexpr int MTILE  = 128;
static constexpr int NTILE  = 64;     // 2 CTAs/SM
static constexpr int KSLAB  = 64;     // K per pipeline slab
static constexpr int KSPLIT = 4;      // K-split factor (wave balancing)
static constexpr int KUNIT  = K_DIM / KSPLIT;    // 1024 k per CTA
static constexpr int NSLABS = KUNIT / KSLAB;     // 16 slabs per CTA
static constexpr int THREADS = 256;   // 8 warps: 4(m) x 2(n), 32x32 each

// fp16 activations (exact GEMM except one f32->f16 rounding)
__device__ __half g_A[M_DIM * K_DIM];                     // 4 MB
// split-K raw partial accumulators (deterministic reduction, no atomics)
__device__ float  g_P[(size_t)KSPLIT * M_DIM * N_DIM];    // 90 MB

// ------------------------------------------------------------------ helpers
__device__ __forceinline__ uint32_t smem_u32(const void* p) {
    uint32_t r;
    asm("{ .reg .u64 t; cvta.to.shared.u64 t, %1; cvt.u32.u64 %0, t; }"
        : "=r"(r) : "l"(p));
    return r;
}

// XOR swizzle on 128B rows (16B chunks) -> conflict-free ldmatrix
#define SWZ(o) ((o) ^ (((o) >> 3) & 0x70))

__device__ __forceinline__ void ldsm_x4(uint32_t& r0, uint32_t& r1,
                                        uint32_t& r2, uint32_t& r3, uint32_t a) {
    asm volatile("ldmatrix.sync.aligned.m8n8.x4.shared.b16 {%0,%1,%2,%3}, [%4];"
                 : "=r"(r0), "=r"(r1), "=r"(r2), "=r"(r3) : "r"(a));
}

__device__ __forceinline__ void mma16816(float* d, const uint32_t* a,
                                         uint32_t b0, uint32_t b1) {
    asm volatile(
        "mma.sync.aligned.m16n8k16.row.col.f32.f16.f16.f32 "
        "{%0,%1,%2,%3}, {%4,%5,%6,%7}, {%8,%9}, {%0,%1,%2,%3};"
        : "+f"(d[0]), "+f"(d[1]), "+f"(d[2]), "+f"(d[3])
        : "r"(a[0]), "r"(a[1]), "r"(a[2]), "r"(a[3]), "r"(b0), "r"(b1));
}

// ------------------------------------------------------------------ SMEM layout
// stage p at p*24576: A tile (128 rows x 128B) then W tile (64 rows x 128B)
static constexpr int STAGE_BYTES = 24576;
static constexpr int W_OFF       = 16384;
static constexpr int SMEM_BYTES  = 2 * STAGE_BYTES + 1024;  // 50176: 2 CTAs/SM

// ------------------------------------------------------------------ convert A
__global__ void convert_A_kernel(const float* __restrict__ in) {
    int n4 = (M_DIM * K_DIM) / 4;
    int i = blockIdx.x * blockDim.x + threadIdx.x;
    if (i >= n4) return;
    float4 v = reinterpret_cast<const float4*>(in)[i];
    __half2 h0 = __floats2half2_rn(v.x, v.y);
    __half2 h1 = __floats2half2_rn(v.z, v.w);
    uint2 u;
    u.x = *reinterpret_cast<uint32_t*>(&h0);
    u.y = *reinterpret_cast<uint32_t*>(&h1);
    reinterpret_cast<uint2*>(g_A)[i] = u;
}

// ------------------------------------------------------------------ GEMM pieces
// dequant W slab held in wq regs -> fp16 STS into stage buffer (exact q-128)
__device__ __forceinline__ void dequant_sts(const int4* wq, uint32_t w_sm, int tid) {
#pragma unroll
    for (int i = 0; i < 4; i++) {
        int li = i * 256 + tid, r = li >> 4, cg = li & 15;
        __half2 h0 = __halves2half2(__int2half_rn(wq[i].x - 128),
                                    __int2half_rn(wq[i].y - 128));
        __half2 h1 = __halves2half2(__int2half_rn(wq[i].z - 128),
                                    __int2half_rn(wq[i].w - 128));
        uint32_t u0 = *reinterpret_cast<uint32_t*>(&h0);
        uint32_t u1 = *reinterpret_cast<uint32_t*>(&h1);
        uint32_t dst = w_sm + SWZ(r * 128 + cg * 8);
        asm volatile("st.shared.v2.b32 [%0], {%1, %2};"
                     :: "r"(dst), "r"(u0), "r"(u1) : "memory");
    }
}

// LDG one W slab into regs (slab index sk in units of 64 k, absolute)
__device__ __forceinline__ void ldg_w(int4* wq, const int4* __restrict__ W,
                                      int n0, int sk, int tid) {
    const size_t wrow = (size_t)K_DIM / 4;
#pragma unroll
    for (int i = 0; i < 4; i++) {
        int li = i * 256 + tid, r = li >> 4, cg = li & 15;
        wq[i] = W[(size_t)(n0 + r) * wrow + sk * (KSLAB / 4) + cg];
    }
}

// issue A-slab cp.async into a stage buffer (absolute k offset)
__device__ __forceinline__ void issue_A(const __half* Abase, int kofs,
                                        uint32_t a_sm, int tid) {
#pragma unroll
    for (int i = 0; i < 4; i++) {
        int li = i * 256 + tid, r = li >> 3, c = li & 7;
        const __half* src = Abase + (size_t)r * K_DIM + kofs + c * 8;
        uint32_t dst = a_sm + SWZ(r * 128 + c * 16);
        asm volatile("cp.async.cg.shared.global [%0], [%1], 16;" :: "r"(dst), "l"(src));
    }
    asm volatile("cp.async.commit_group;" ::: "memory");
}

__global__ void __launch_bounds__(THREADS, 2)
qlinear_hmma_kernel(const int4* __restrict__ W) {
    extern __shared__ char smem_raw[];
    const uint32_t smem = (smem_u32(smem_raw) + 1023u) & ~1023u;

    const int tid  = threadIdx.x;
    const int wid  = tid >> 5;
    const int lane = tid & 31;
    const int wm   = wid >> 1;          // 0..3 : 32-row M strip
    const int wn   = wid & 1;           // 0..1 : 32-col N strip
    const int m0   = blockIdx.x * MTILE;    // m fastest -> weight L2 reuse
    const int n0   = blockIdx.y * NTILE;
    const int kz   = blockIdx.z;            // k-split index
    const int sk0  = kz * NSLABS;           // first slab (units of 64 k)

    const __half* Abase = g_A + (size_t)m0 * K_DIM;

    float acc[2][4][4];
#pragma unroll
    for (int i = 0; i < 2; i++)
#pragma unroll
        for (int j = 0; j < 4; j++)
#pragma unroll
            for (int e = 0; e < 4; e++) acc[i][j][e] = 0.f;

    int4 wq[4];   // one W slab in flight

    // ---- prologue --------------------------------------------------------
    ldg_w(wq, W, n0, sk0 + 0, tid);
    issue_A(Abase, (sk0 + 0) * KSLAB, smem, tid);          // A(0) -> stage 0
    dequant_sts(wq, smem + W_OFF, tid);                    // W(0) -> stage 0
    ldg_w(wq, W, n0, sk0 + 1, tid);                        // W(1) staged in regs

    // ---- main loop -------------------------------------------------------
#pragma unroll 1
    for (int s = 0; s < NSLABS; s++) {
        const int p = s & 1;
        const uint32_t a_sm = smem + p * STAGE_BYTES;
        const uint32_t w_sm = a_sm + W_OFF;

        asm volatile("cp.async.wait_group 0;" ::: "memory");   // A(s) arrived
        __syncthreads();   // stage p ready; stage p^1 free

        if (s + 1 < NSLABS) {
            issue_A(Abase, (sk0 + s + 1) * KSLAB,
                    smem + (p ^ 1) * STAGE_BYTES, tid);
            dequant_sts(wq, smem + (p ^ 1) * STAGE_BYTES + W_OFF, tid);
            if (s + 2 < NSLABS)
                ldg_w(wq, W, n0, sk0 + s + 2, tid);
        }

        // compute slab s: 4 k-steps of 16
#pragma unroll
        for (int ks = 0; ks < 4; ks++) {
            const int chunk = ks * 2 + (lane >> 4);
            uint32_t a[2][4];
#pragma unroll
            for (int mt = 0; mt < 2; mt++) {
                int row = wm * 32 + mt * 16 + (lane & 15);
                ldsm_x4(a[mt][0], a[mt][1], a[mt][2], a[mt][3],
                        a_sm + SWZ(row * 128 + chunk * 16));
            }
            uint32_t b[4][2];
#pragma unroll
            for (int j = 0; j < 2; j++) {
                int row = wn * 32 + j * 16 + (lane & 15);
                uint32_t t0, t1, t2, t3;
                ldsm_x4(t0, t1, t2, t3, w_sm + SWZ(row * 128 + chunk * 16));
                b[j * 2 + 0][0] = t0;  b[j * 2 + 1][0] = t1;
                b[j * 2 + 0][1] = t2;  b[j * 2 + 1][1] = t3;
            }
#pragma unroll
            for (int mt = 0; mt < 2; mt++)
#pragma unroll
                for (int nt = 0; nt < 4; nt++)
                    mma16816(acc[mt][nt], a[mt], b[nt][0], b[nt][1]);
        }
    }

    // ---- epilogue: raw partial -> g_P[kz] --------------------------------
    float* Pbase = g_P + (size_t)kz * (M_DIM * N_DIM);
    const int ncb = n0 + wn * 32;
#pragma unroll
    for (int mt = 0; mt < 2; mt++) {
        int row = m0 + wm * 32 + mt * 16 + (lane >> 2);
#pragma unroll
        for (int nt = 0; nt < 4; nt++) {
            int col = ncb + nt * 8 + (lane & 3) * 2;
            float2 v0, v1;
            v0.x = acc[mt][nt][0];  v0.y = acc[mt][nt][1];
            v1.x = acc[mt][nt][2];  v1.y = acc[mt][nt][3];
            *reinterpret_cast<float2*>(Pbase + (size_t)row * N_DIM + col)       = v0;
            *reinterpret_cast<float2*>(Pbase + (size_t)(row + 8) * N_DIM + col) = v1;
        }
    }
}

// ------------------------------------------------------------------ reduction
// out = bias + scale * (p0 + p1 + p2 + p3), vectorized float4; deterministic
__global__ void reduce_kernel(const float* __restrict__ scale,
                              const float* __restrict__ bias,
                              float* __restrict__ out) {
    constexpr int N4      = N_DIM / 4;                 // 2752
    constexpr int TOTAL4  = (M_DIM * N_DIM) / 4;       // 1409024
    int i = blockIdx.x * blockDim.x + threadIdx.x;
    if (i >= TOTAL4) return;

    const float4* P = reinterpret_cast<const float4*>(g_P);
    float4 s0 = P[i];
    float4 s1 = P[i + TOTAL4];
    float4 s2 = P[i + 2 * TOTAL4];
    float4 s3 = P[i + 3 * TOTAL4];
    float4 s;
    s.x = (s0.x + s1.x) + (s2.x + s3.x);
    s.y = (s0.y + s1.y) + (s2.y + s3.y);
    s.z = (s0.z + s1.z) + (s2.z + s3.z);
    s.w = (s0.w + s1.w) + (s2.w + s3.w);

    int nc = i % N4;
    float4 sc = reinterpret_cast<const float4*>(scale)[nc];
    float4 bi = reinterpret_cast<const float4*>(bias)[nc];
    float4 r;
    r.x = fmaf(sc.x, s.x, bi.x);
    r.y = fmaf(sc.y, s.y, bi.y);
    r.z = fmaf(sc.z, s.z, bi.z);
    r.w = fmaf(sc.w, s.w, bi.w);
    reinterpret_cast<float4*>(out)[i] = r;
}

// ------------------------------------------------------------------ launch
extern "C" void kernel_launch(void* const* d_in, const int* in_sizes, int n_in,
                              void* d_out, int out_size) {
    (void)in_sizes; (void)n_in; (void)out_size;
    const float* input = (const float*)d_in[0];
    const int4*  W     = (const int4*)d_in[1];
    const float* scale = (const float*)d_in[2];
    const float* bias  = (const float*)d_in[3];
    float* out = (float*)d_out;

    convert_A_kernel<<<(M_DIM * K_DIM / 4 + 255) / 256, 256>>>(input);

    cudaFuncSetAttribute(qlinear_hmma_kernel,
                         cudaFuncAttributeMaxDynamicSharedMemorySize, SMEM_BYTES);
    dim3 grid(M_DIM / MTILE, N_DIM / NTILE, KSPLIT);   // m fastest: W L2 reuse
    qlinear_hmma_kernel<<<grid, THREADS, SMEM_BYTES>>>(W);

    constexpr int TOTAL4 = (M_DIM * N_DIM) / 4;
    reduce_kernel<<<(TOTAL4 + 255) / 256, 256>>>(scale, bias, out);
}

// round 11
// speedup vs baseline: 1.0760x; 1.0608x over previous
#include <cuda_runtime.h>
#include <cuda_fp16.h>
#include <cstdint>
#include <cstddef>

// Problem dims (fixed by the reference)
static constexpr int M_DIM  = 512;    // B*S
static constexpr int K_DIM  = 4096;   // IN
static constexpr int N_DIM  = 11008;  // OUT
static constexpr int MTILE  = 128;
static constexpr int NTILE  = 64;     // 2 CTAs/SM
static constexpr int KSLAB  = 64;     // K per pipeline slab
static constexpr int KSPLIT = 2;      // K-split factor (3 clean waves)
static constexpr int KUNIT  = K_DIM / KSPLIT;    // 2048 k per CTA
static constexpr int NSLABS = KUNIT / KSLAB;     // 32 slabs per CTA
static constexpr int STAGES = 3;      // cp.async pipeline depth
static constexpr int THREADS = 256;   // 8 warps: 4(m) x 2(n), 32x32 each

// fp16 activations (exact GEMM except one f32->f16 rounding)
__device__ __half g_A[M_DIM * K_DIM];                     // 4 MB
// split-K raw partial accumulators (deterministic reduction, no atomics)
__device__ float  g_P[(size_t)KSPLIT * M_DIM * N_DIM];    // 45 MB

// ------------------------------------------------------------------ helpers
__device__ __forceinline__ uint32_t smem_u32(const void* p) {
    uint32_t r;
    asm("{ .reg .u64 t; cvta.to.shared.u64 t, %1; cvt.u32.u64 %0, t; }"
        : "=r"(r) : "l"(p));
    return r;
}

__device__ __forceinline__ uint32_t prmt(uint32_t a, uint32_t b, uint32_t s) {
    uint32_t r;
    asm("prmt.b32 %0, %1, %2, %3;" : "=r"(r) : "r"(a), "r"(b), "r"(s));
    return r;
}

__device__ __forceinline__ uint32_t hsub2(uint32_t a, uint32_t b) {
    uint32_t r;
    asm("sub.rn.f16x2 %0, %1, %2;" : "=r"(r) : "r"(a), "r"(b));
    return r;
}

// XOR swizzle on 128B rows (16B chunks) -> conflict-free ldmatrix
#define SWZ(o) ((o) ^ (((o) >> 3) & 0x70))

__device__ __forceinline__ void ldsm_x4(uint32_t& r0, uint32_t& r1,
                                        uint32_t& r2, uint32_t& r3, uint32_t a) {
    asm volatile("ldmatrix.sync.aligned.m8n8.x4.shared.b16 {%0,%1,%2,%3}, [%4];"
                 : "=r"(r0), "=r"(r1), "=r"(r2), "=r"(r3) : "r"(a));
}

__device__ __forceinline__ void mma16816(float* d, const uint32_t* a,
                                         uint32_t b0, uint32_t b1) {
    asm volatile(
        "mma.sync.aligned.m16n8k16.row.col.f32.f16.f16.f32 "
        "{%0,%1,%2,%3}, {%4,%5,%6,%7}, {%8,%9}, {%0,%1,%2,%3};"
        : "+f"(d[0]), "+f"(d[1]), "+f"(d[2]), "+f"(d[3])
        : "r"(a[0]), "r"(a[1]), "r"(a[2]), "r"(a[3]), "r"(b0), "r"(b1));
}

// ------------------------------------------------------------------ SMEM layout
// stage: A panel (128 rows x 128B) at +0, W panel (64 rows x 128B) at +16384
static constexpr int W_OFF       = 16384;
static constexpr int STAGE_BYTES = 24576;
static constexpr int SMEM_BYTES  = STAGES * STAGE_BYTES + 1024;  // 74752: 2/SM

// ------------------------------------------------------------------ convert A
__global__ void convert_A_kernel(const float* __restrict__ in) {
    int n4 = (M_DIM * K_DIM) / 4;
    int i = blockIdx.x * blockDim.x + threadIdx.x;
    if (i >= n4) return;
    float4 v = reinterpret_cast<const float4*>(in)[i];
    __half2 h0 = __floats2half2_rn(v.x, v.y);
    __half2 h1 = __floats2half2_rn(v.z, v.w);
    uint2 u;
    u.x = *reinterpret_cast<uint32_t*>(&h0);
    u.y = *reinterpret_cast<uint32_t*>(&h1);
    reinterpret_cast<uint2*>(g_A)[i] = u;
}

// ------------------------------------------------------------------ GEMM pieces
// Bit-trick dequant: q in [0,256) -> fp16 bits (0x6400|q) == 1024+q exactly;
// subtract 1152.0h -> exact (q-128). 3 ops per 2 values, no I2F.
__device__ __forceinline__ void dequant_sts(const int4* wq, uint32_t w_sm, int tid) {
#pragma unroll
    for (int i = 0; i < 4; i++) {
        int li = i * 256 + tid, r = li >> 4, cg = li & 15;
        uint32_t u0 = hsub2(prmt((uint32_t)wq[i].x, (uint32_t)wq[i].y, 0x5410u)
                                | 0x64006400u, 0x64806480u);
        uint32_t u1 = hsub2(prmt((uint32_t)wq[i].z, (uint32_t)wq[i].w, 0x5410u)
                                | 0x64006400u, 0x64806480u);
        uint32_t dst = w_sm + SWZ(r * 128 + cg * 8);
        asm volatile("st.shared.v2.b32 [%0], {%1, %2};"
                     :: "r"(dst), "r"(u0), "r"(u1) : "memory");
    }
}

// LDG one W slab into regs (slab index sk in units of 64 k, absolute)
__device__ __forceinline__ void ldg_w(int4* wq, const int4* __restrict__ W,
                                      int n0, int sk, int tid) {
    const size_t wrow = (size_t)K_DIM / 4;
#pragma unroll
    for (int i = 0; i < 4; i++) {
        int li = i * 256 + tid, r = li >> 4, cg = li & 15;
        wq[i] = W[(size_t)(n0 + r) * wrow + sk * (KSLAB / 4) + cg];
    }
}

// issue A-slab cp.async into a stage buffer (absolute k offset); one group
__device__ __forceinline__ void issue_A(const __half* Abase, int kofs,
                                        uint32_t a_sm, int tid) {
#pragma unroll
    for (int i = 0; i < 4; i++) {
        int li = i * 256 + tid, r = li >> 3, c = li & 7;
        const __half* src = Abase + (size_t)r * K_DIM + kofs + c * 8;
        uint32_t dst = a_sm + SWZ(r * 128 + c * 16);
        asm volatile("cp.async.cg.shared.global [%0], [%1], 16;" :: "r"(dst), "l"(src));
    }
    asm volatile("cp.async.commit_group;" ::: "memory");
}

__global__ void __launch_bounds__(THREADS, 2)
qlinear_hmma_kernel(const int4* __restrict__ W) {
    extern __shared__ char smem_raw[];
    const uint32_t smem = (smem_u32(smem_raw) + 1023u) & ~1023u;

    const int tid  = threadIdx.x;
    const int wid  = tid >> 5;
    const int lane = tid & 31;
    const int wm   = wid >> 1;          // 0..3 : 32-row M strip
    const int wn   = wid & 1;           // 0..1 : 32-col N strip
    const int m0   = blockIdx.x * MTILE;    // m fastest -> weight L2 reuse
    const int n0   = blockIdx.y * NTILE;
    const int kz   = blockIdx.z;            // k-split index
    const int sk0  = kz * NSLABS;           // first slab (units of 64 k)

    const __half* Abase = g_A + (size_t)m0 * K_DIM;

    float acc[2][4][4];
#pragma unroll
    for (int i = 0; i < 2; i++)
#pragma unroll
        for (int j = 0; j < 4; j++)
#pragma unroll
            for (int e = 0; e < 4; e++) acc[i][j][e] = 0.f;

    int4 wq[4];   // one W slab in flight

    // ---- prologue: A(0),A(1) committed; W(0) STS'd; wq=W(1) --------------
    ldg_w(wq, W, n0, sk0 + 0, tid);
    issue_A(Abase, (sk0 + 0) * KSLAB, smem, tid);
    issue_A(Abase, (sk0 + 1) * KSLAB, smem + STAGE_BYTES, tid);
    dequant_sts(wq, smem + W_OFF, tid);
    ldg_w(wq, W, n0, sk0 + 1, tid);

    // ---- main loop: 3-stage A pipeline, W staged one ahead ----------------
#pragma unroll 1
    for (int s = 0; s < NSLABS; s++) {
        const uint32_t a_sm = smem + (s % STAGES) * STAGE_BYTES;
        const uint32_t w_sm = a_sm + W_OFF;

        if (s + 2 < NSLABS)
            asm volatile("cp.async.wait_group 1;" ::: "memory");  // A(s) done
        else
            asm volatile("cp.async.wait_group 0;" ::: "memory");
        __syncthreads();   // stage s%3 ready; stage (s+2)%3 free (readers done)

        if (s + 1 < NSLABS) {
            if (s + 2 < NSLABS)
                issue_A(Abase, (sk0 + s + 2) * KSLAB,
                        smem + ((s + 2) % STAGES) * STAGE_BYTES, tid);
            dequant_sts(wq, smem + ((s + 1) % STAGES) * STAGE_BYTES + W_OFF, tid);
            if (s + 2 < NSLABS)
                ldg_w(wq, W, n0, sk0 + s + 2, tid);
        }

        // compute slab s: 4 k-steps of 16
#pragma unroll
        for (int ks = 0; ks < 4; ks++) {
            const int chunk = ks * 2 + (lane >> 4);
            uint32_t a[2][4];
#pragma unroll
            for (int mt = 0; mt < 2; mt++) {
                int row = wm * 32 + mt * 16 + (lane & 15);
                ldsm_x4(a[mt][0], a[mt][1], a[mt][2], a[mt][3],
                        a_sm + SWZ(row * 128 + chunk * 16));
            }
            uint32_t b[4][2];
#pragma unroll
            for (int j = 0; j < 2; j++) {
                int row = wn * 32 + j * 16 + (lane & 15);
                uint32_t t0, t1, t2, t3;
                ldsm_x4(t0, t1, t2, t3, w_sm + SWZ(row * 128 + chunk * 16));
                b[j * 2 + 0][0] = t0;  b[j * 2 + 1][0] = t1;
                b[j * 2 + 0][1] = t2;  b[j * 2 + 1][1] = t3;
            }
#pragma unroll
            for (int mt = 0; mt < 2; mt++)
#pragma unroll
                for (int nt = 0; nt < 4; nt++)
                    mma16816(acc[mt][nt], a[mt], b[nt][0], b[nt][1]);
        }
    }

    // ---- epilogue: raw partial -> g_P[kz] --------------------------------
    float* Pbase = g_P + (size_t)kz * (M_DIM * N_DIM);
    const int ncb = n0 + wn * 32;
#pragma unroll
    for (int mt = 0; mt < 2; mt++) {
        int row = m0 + wm * 32 + mt * 16 + (lane >> 2);
#pragma unroll
        for (int nt = 0; nt < 4; nt++) {
            int col = ncb + nt * 8 + (lane & 3) * 2;
            float2 v0, v1;
            v0.x = acc[mt][nt][0];  v0.y = acc[mt][nt][1];
            v1.x = acc[mt][nt][2];  v1.y = acc[mt][nt][3];
            *reinterpret_cast<float2*>(Pbase + (size_t)row * N_DIM + col)       = v0;
            *reinterpret_cast<float2*>(Pbase + (size_t)(row + 8) * N_DIM + col) = v1;
        }
    }
}

// ------------------------------------------------------------------ reduction
// out = bias + scale * (p0 + p1), vectorized float4; deterministic order
__global__ void reduce_kernel(const float* __restrict__ scale,
                              const float* __restrict__ bias,
                              float* __restrict__ out) {
    constexpr int N4     = N_DIM / 4;              // 2752
    constexpr int TOTAL4 = (M_DIM * N_DIM) / 4;    // 1409024
    int i = blockIdx.x * blockDim.x + threadIdx.x;
    if (i >= TOTAL4) return;

    const float4* P = reinterpret_cast<const float4*>(g_P);
    float4 s0 = P[i];
    float4 s1 = P[i + TOTAL4];
    float4 s;
    s.x = s0.x + s1.x;
    s.y = s0.y + s1.y;
    s.z = s0.z + s1.z;
    s.w = s0.w + s1.w;

    int nc = i % N4;
    float4 sc = reinterpret_cast<const float4*>(scale)[nc];
    float4 bi = reinterpret_cast<const float4*>(bias)[nc];
    float4 r;
    r.x = fmaf(sc.x, s.x, bi.x);
    r.y = fmaf(sc.y, s.y, bi.y);
    r.z = fmaf(sc.z, s.z, bi.z);
    r.w = fmaf(sc.w, s.w, bi.w);
    reinterpret_cast<float4*>(out)[i] = r;
}

// ------------------------------------------------------------------ launch
extern "C" void kernel_launch(void* const* d_in, const int* in_sizes, int n_in,
                              void* d_out, int out_size) {
    (void)in_sizes; (void)n_in; (void)out_size;
    const float* input = (const float*)d_in[0];
    const int4*  W     = (const int4*)d_in[1];
    const float* scale = (const float*)d_in[2];
    const float* bias  = (const float*)d_in[3];
    float* out = (float*)d_out;

    convert_A_kernel<<<(M_DIM * K_DIM / 4 + 255) / 256, 256>>>(input);

    cudaFuncSetAttribute(qlinear_hmma_kernel,
                         cudaFuncAttributeMaxDynamicSharedMemorySize, SMEM_BYTES);
    dim3 grid(M_DIM / MTILE, N_DIM / NTILE, KSPLIT);   // m fastest: W L2 reuse
    qlinear_hmma_kernel<<<grid, THREADS, SMEM_BYTES>>>(W);

    constexpr int TOTAL4 = (M_DIM * N_DIM) / 4;
    reduce_kernel<<<(TOTAL4 + 255) / 256, 256>>>(scale, bias, out);
}